// round 3
// baseline (speedup 1.0000x reference)
#include <cuda_runtime.h>
#include <math.h>

#define N_NODES 50000
#define E_EDGES 1600000
#define NEG_SLOPE 0.2f
#define BN_EPS 1e-5f

// ---------------- scratch (static device globals; no allocation) ------------
__device__ float g_bufA[(size_t)N_NODES * 128];
__device__ float g_bufB[(size_t)N_NODES * 128];
__device__ float g_bufC[(size_t)N_NODES * 128];
__device__ float g_bufF[(size_t)N_NODES * 64];
__device__ float g_als[N_NODES * 2];
__device__ float g_ald[N_NODES * 2];
__device__ float g_wc[128 * 128];
__device__ int   g_deg[N_NODES];
__device__ int   g_roff[N_NODES + 1];
__device__ int   g_cur[N_NODES];
__device__ int   g_esrc[E_EDGES];

// ---------------- helpers ----------------------------------------------------
__device__ __forceinline__ float lrelu(float x) {
    return x > 0.0f ? x : NEG_SLOPE * x;
}

// ---------------- CSR build ---------------------------------------------------
__global__ void hist_kernel(const int* __restrict__ dst, int* __restrict__ deg)
{
    int e = blockIdx.x * blockDim.x + threadIdx.x;
    if (e < E_EDGES) atomicAdd(&deg[dst[e]], 1);
}

__global__ __launch_bounds__(1024) void scan_kernel(
    const int* __restrict__ deg, int* __restrict__ roff, int* __restrict__ cur)
{
    __shared__ int part[1024];
    const int CH = (N_NODES + 1023) / 1024;
    int t = threadIdx.x;
    int base = t * CH;
    int sum = 0;
    for (int i = 0; i < CH; i++) {
        int idx = base + i;
        if (idx < N_NODES) sum += deg[idx];
    }
    part[t] = sum;
    __syncthreads();
    for (int off = 1; off < 1024; off <<= 1) {
        int v = (t >= off) ? part[t - off] : 0;
        __syncthreads();
        part[t] += v;
        __syncthreads();
    }
    int run = part[t] - sum;
    for (int i = 0; i < CH; i++) {
        int idx = base + i;
        if (idx < N_NODES) {
            roff[idx] = run;
            cur[idx]  = run;
            run += deg[idx];
        }
    }
    if (t == 1023) roff[N_NODES] = run;
}

__global__ void scatter_kernel(const int* __restrict__ src,
                               const int* __restrict__ dst,
                               int* __restrict__ cur, int* __restrict__ esrc)
{
    int e = blockIdx.x * blockDim.x + threadIdx.x;
    if (e >= E_EDGES) return;
    int d = dst[e];
    int p = atomicAdd(&cur[d], 1);
    esrc[p] = src[e];
}

// ---------------- SGEMM: C[M,NC] = A[M,K] @ B[K,NC], NC == BN_ ---------------
template<int BM_, int BN_, int TM_, int TN_, int THREADS>
__global__ __launch_bounds__(THREADS) void sgemm_t(
    const float* __restrict__ A, const float* __restrict__ B,
    float* __restrict__ C, int M, int K, int NC)
{
    const int BK_ = 16;
    __shared__ float As[BK_][BM_];
    __shared__ float Bs[BK_][BN_];

    int tid = threadIdx.x;
    int rowBase = blockIdx.x * BM_;
    const int TX = BN_ / TN_;
    int tx = tid % TX;
    int ty = tid / TX;

    float acc[TM_][TN_];
    #pragma unroll
    for (int i = 0; i < TM_; i++)
        #pragma unroll
        for (int j = 0; j < TN_; j++) acc[i][j] = 0.0f;

    const int AROWS = THREADS / 4;       // rows of A tile loaded per pass
    int ar = tid >> 2;
    int ac = (tid & 3) * 4;
    const int BF4 = BN_ / 4;             // float4 per B row
    const int BROWS = THREADS / BF4;     // B rows per pass
    int br = tid / BF4;
    int bc = (tid % BF4) * 4;

    for (int k0 = 0; k0 < K; k0 += BK_) {
        #pragma unroll
        for (int i = 0; i < BM_ / AROWS; i++) {
            int r  = ar + i * AROWS;
            int gr = rowBase + r;
            float4 v = make_float4(0.f, 0.f, 0.f, 0.f);
            if (gr < M) v = *(const float4*)(A + (size_t)gr * K + k0 + ac);
            As[ac + 0][r] = v.x;
            As[ac + 1][r] = v.y;
            As[ac + 2][r] = v.z;
            As[ac + 3][r] = v.w;
        }
        #pragma unroll
        for (int i = 0; i < BK_ / BROWS; i++) {
            int r = br + i * BROWS;
            float4 v = *(const float4*)(B + (size_t)(k0 + r) * NC + bc);
            *(float4*)&Bs[r][bc] = v;
        }
        __syncthreads();

        #pragma unroll
        for (int kk = 0; kk < BK_; kk++) {
            float4 a0 = *(const float4*)&As[kk][ty * TM_];
            float4 a1 = *(const float4*)&As[kk][ty * TM_ + 4];
            float4 b0 = *(const float4*)&Bs[kk][tx * TN_];
            float4 b1 = *(const float4*)&Bs[kk][tx * TN_ + 4];
            float a[TM_] = {a0.x, a0.y, a0.z, a0.w, a1.x, a1.y, a1.z, a1.w};
            float b[TN_] = {b0.x, b0.y, b0.z, b0.w, b1.x, b1.y, b1.z, b1.w};
            #pragma unroll
            for (int i = 0; i < TM_; i++)
                #pragma unroll
                for (int j = 0; j < TN_; j++)
                    acc[i][j] = fmaf(a[i], b[j], acc[i][j]);
        }
        __syncthreads();
    }

    #pragma unroll
    for (int i = 0; i < TM_; i++) {
        int gr = rowBase + ty * TM_ + i;
        if (gr < M) {
            float* cp = C + (size_t)gr * NC + tx * TN_;
            *(float4*)(cp + 0) = make_float4(acc[i][0], acc[i][1], acc[i][2], acc[i][3]);
            *(float4*)(cp + 4) = make_float4(acc[i][4], acc[i][5], acc[i][6], acc[i][7]);
        }
    }
}

// ---------------- GAT attention-logit precompute -----------------------------
__global__ void compute_al_kernel(
    const float* __restrict__ h, const float* __restrict__ a_src,
    const float* __restrict__ a_dst, float* __restrict__ als,
    float* __restrict__ ald)
{
    int warp = (blockIdx.x * blockDim.x + threadIdx.x) >> 5;
    int lane = threadIdx.x & 31;
    if (warp >= N_NODES) return;

    float4 hv = *(const float4*)(h + (size_t)warp * 128 + lane * 4);
    float4 as = *(const float4*)(a_src + lane * 4);
    float4 ad = *(const float4*)(a_dst + lane * 4);
    float ss = hv.x * as.x + hv.y * as.y + hv.z * as.z + hv.w * as.w;
    float sd = hv.x * ad.x + hv.y * ad.y + hv.z * ad.z + hv.w * ad.w;
    #pragma unroll
    for (int o = 8; o; o >>= 1) {
        ss += __shfl_xor_sync(0xffffffffu, ss, o);
        sd += __shfl_xor_sync(0xffffffffu, sd, o);
    }
    if (lane == 0)  { als[warp * 2 + 0] = ss; ald[warp * 2 + 0] = sd; }
    if (lane == 16) { als[warp * 2 + 1] = ss; ald[warp * 2 + 1] = sd; }
}

// ---------------- fused GAT gather (softmax + aggregate + bias + act) --------
// one warp per destination node; lane owns 4 feature columns.
// Single merged pass: unnormalized exp-weights accumulated with features,
// normalized at the end. No max-subtraction: logits are O(10) -> exp safe.
__global__ __launch_bounds__(256) void gat_gather_kernel(
    const int* __restrict__ roff, const int* __restrict__ esrc,
    const float* __restrict__ als, const float* __restrict__ ald,
    const float* __restrict__ h, const float* __restrict__ bias,
    float* __restrict__ out, int relu)
{
    int d = (blockIdx.x * blockDim.x + threadIdx.x) >> 5;
    int lane = threadIdx.x & 31;
    if (d >= N_NODES) return;

    float2 ad = *(const float2*)(ald + 2 * d);
    float2 a_self = *(const float2*)(als + 2 * d);
    int head = (lane >= 16);
    float adh = head ? ad.y : ad.x;

    // self-loop term
    float w_self0 = expf(lrelu(a_self.x + ad.x));
    float w_self1 = expf(lrelu(a_self.y + ad.y));
    float s0 = w_self0, s1 = w_self1;
    float wsh = head ? w_self1 : w_self0;

    float4 hv = *(const float4*)(h + (size_t)d * 128 + lane * 4);
    float4 acc;
    acc.x = wsh * hv.x;
    acc.y = wsh * hv.y;
    acc.z = wsh * hv.z;
    acc.w = wsh * hv.w;

    int beg = roff[d], end = roff[d + 1];
    int i = beg;
    for (; i + 1 < end; i += 2) {
        int sA = __ldg(esrc + i);
        int sB = __ldg(esrc + i + 1);
        float2 aA = *(const float2*)(als + 2 * sA);
        float2 aB = *(const float2*)(als + 2 * sB);
        float4 vA = *(const float4*)(h + (size_t)sA * 128 + lane * 4);
        float4 vB = *(const float4*)(h + (size_t)sB * 128 + lane * 4);
        float wA0 = expf(lrelu(aA.x + ad.x));
        float wA1 = expf(lrelu(aA.y + ad.y));
        float wB0 = expf(lrelu(aB.x + ad.x));
        float wB1 = expf(lrelu(aB.y + ad.y));
        s0 += wA0 + wB0;
        s1 += wA1 + wB1;
        float whA = head ? wA1 : wA0;
        float whB = head ? wB1 : wB0;
        acc.x = fmaf(whA, vA.x, acc.x);
        acc.y = fmaf(whA, vA.y, acc.y);
        acc.z = fmaf(whA, vA.z, acc.z);
        acc.w = fmaf(whA, vA.w, acc.w);
        acc.x = fmaf(whB, vB.x, acc.x);
        acc.y = fmaf(whB, vB.y, acc.y);
        acc.z = fmaf(whB, vB.z, acc.z);
        acc.w = fmaf(whB, vB.w, acc.w);
    }
    if (i < end) {
        int s = __ldg(esrc + i);
        float2 a = *(const float2*)(als + 2 * s);
        float4 v = *(const float4*)(h + (size_t)s * 128 + lane * 4);
        float w0 = expf(lrelu(a.x + ad.x));
        float w1 = expf(lrelu(a.y + ad.y));
        s0 += w0;
        s1 += w1;
        float wh = head ? w1 : w0;
        acc.x = fmaf(wh, v.x, acc.x);
        acc.y = fmaf(wh, v.y, acc.y);
        acc.z = fmaf(wh, v.z, acc.z);
        acc.w = fmaf(wh, v.w, acc.w);
    }

    float inv = 1.0f / (head ? s1 : s0);
    float4 b = *(const float4*)(bias + lane * 4);
    acc.x = fmaf(acc.x, inv, b.x);
    acc.y = fmaf(acc.y, inv, b.y);
    acc.z = fmaf(acc.z, inv, b.z);
    acc.w = fmaf(acc.w, inv, b.w);
    if (relu) {
        acc.x = fmaxf(acc.x, 0.0f);
        acc.y = fmaxf(acc.y, 0.0f);
        acc.z = fmaxf(acc.z, 0.0f);
        acc.w = fmaxf(acc.w, 0.0f);
    }
    *(float4*)(out + (size_t)d * 128 + lane * 4) = acc;
}

// ---------------- weight concat for fused SAGE GEMM --------------------------
// wc[k][0:64] = wl[k][:], wc[k][64:128] = wr[k][:]
__global__ void concat_w_kernel(const float* __restrict__ wl,
                                const float* __restrict__ wr,
                                float* __restrict__ wc, int K)
{
    int i = blockIdx.x * blockDim.x + threadIdx.x;
    if (i >= K * 64) return;
    int k = i >> 6, c = i & 63;
    wc[k * 128 + c]      = wl[i];
    wc[k * 128 + 64 + c] = wr[i];
}

// ---------------- fused SAGE gather (mean + bias + root + relu [+ BN]) -------
// S holds [y | r] per row (stride 128). One warp per dst; lane owns 2 cols.
__global__ __launch_bounds__(256) void sage_gather_kernel(
    const int* __restrict__ roff, const int* __restrict__ esrc,
    const float* __restrict__ S, const float* __restrict__ bl,
    float* __restrict__ out,
    const float* __restrict__ gamma, const float* __restrict__ beta,
    const float* __restrict__ mean, const float* __restrict__ var,
    int do_bn)
{
    int d = (blockIdx.x * blockDim.x + threadIdx.x) >> 5;
    int lane = threadIdx.x & 31;
    if (d >= N_NODES) return;

    int beg = roff[d], end = roff[d + 1];
    float ax = 0.0f, ay = 0.0f;
    int i = beg;
    for (; i + 1 < end; i += 2) {
        int sA = __ldg(esrc + i);
        int sB = __ldg(esrc + i + 1);
        float2 vA = *(const float2*)(S + (size_t)sA * 128 + lane * 2);
        float2 vB = *(const float2*)(S + (size_t)sB * 128 + lane * 2);
        ax += vA.x + vB.x;
        ay += vA.y + vB.y;
    }
    if (i < end) {
        int s = __ldg(esrc + i);
        float2 v = *(const float2*)(S + (size_t)s * 128 + lane * 2);
        ax += v.x;
        ay += v.y;
    }
    float invc = 1.0f / fmaxf((float)(end - beg), 1.0f);
    int c = lane * 2;
    float2 bb = *(const float2*)(bl + c);
    float2 rr = *(const float2*)(S + (size_t)d * 128 + 64 + c);
    float vx = fmaxf(ax * invc + bb.x + rr.x, 0.0f);
    float vy = fmaxf(ay * invc + bb.y + rr.y, 0.0f);
    if (do_bn) {
        float sx = gamma[c]     * rsqrtf(var[c]     + BN_EPS);
        float sy = gamma[c + 1] * rsqrtf(var[c + 1] + BN_EPS);
        vx = (vx - mean[c])     * sx + beta[c];
        vy = (vy - mean[c + 1]) * sy + beta[c + 1];
    }
    *(float2*)(out + (size_t)d * 64 + c) = make_float2(vx, vy);
}

// ---------------- host orchestration -----------------------------------------
extern "C" void kernel_launch(void* const* d_in, const int* in_sizes, int n_in,
                              void* d_out, int out_size)
{
    const float* x      = (const float*)d_in[0];
    const int*   ei     = (const int*)d_in[1];
    const float* W1     = (const float*)d_in[2];
    const float* a_src1 = (const float*)d_in[3];
    const float* a_dst1 = (const float*)d_in[4];
    const float* b1     = (const float*)d_in[5];
    const float* W2     = (const float*)d_in[6];
    const float* a_src2 = (const float*)d_in[7];
    const float* a_dst2 = (const float*)d_in[8];
    const float* b2     = (const float*)d_in[9];
    const float* s1wl   = (const float*)d_in[10];
    const float* s1bl   = (const float*)d_in[11];
    const float* s1wr   = (const float*)d_in[12];
    const float* s2wl   = (const float*)d_in[13];
    const float* s2bl   = (const float*)d_in[14];
    const float* s2wr   = (const float*)d_in[15];
    const float* bng    = (const float*)d_in[16];
    const float* bnb    = (const float*)d_in[17];
    const float* bnm    = (const float*)d_in[18];
    const float* bnv    = (const float*)d_in[19];
    float* out = (float*)d_out;

    const int* src = ei;
    const int* dst = ei + E_EDGES;

    float *A, *B, *C, *F, *als, *ald, *wc;
    int *deg, *roff, *cur, *esrc;
    cudaGetSymbolAddress((void**)&A,    g_bufA);
    cudaGetSymbolAddress((void**)&B,    g_bufB);
    cudaGetSymbolAddress((void**)&C,    g_bufC);
    cudaGetSymbolAddress((void**)&F,    g_bufF);
    cudaGetSymbolAddress((void**)&als,  g_als);
    cudaGetSymbolAddress((void**)&ald,  g_ald);
    cudaGetSymbolAddress((void**)&wc,   g_wc);
    cudaGetSymbolAddress((void**)&deg,  g_deg);
    cudaGetSymbolAddress((void**)&roff, g_roff);
    cudaGetSymbolAddress((void**)&cur,  g_cur);
    cudaGetSymbolAddress((void**)&esrc, g_esrc);

    // ---- CSR build (by dst) ----
    cudaMemsetAsync(deg, 0, N_NODES * sizeof(int), 0);
    hist_kernel<<<(E_EDGES + 255) / 256, 256>>>(dst, deg);
    scan_kernel<<<1, 1024>>>(deg, roff, cur);
    scatter_kernel<<<(E_EDGES + 255) / 256, 256>>>(src, dst, cur, esrc);

    int gemmBlocks   = (N_NODES + 127) / 128;
    int gatherBlocks = (N_NODES * 32 + 255) / 256;
    int alBlocks     = (N_NODES + 7) / 8;

    // ---- GAT layer 1: h1 = x@W1 -> A, gather -> B (relu) ----
    sgemm_t<128, 128, 8, 8, 256><<<gemmBlocks, 256>>>(x, W1, A, N_NODES, 256, 128);
    compute_al_kernel<<<alBlocks, 256>>>(A, a_src1, a_dst1, als, ald);
    gat_gather_kernel<<<gatherBlocks, 256>>>(roff, esrc, als, ald, A, b1, B, 1);

    // ---- GAT layer 2: h2 = B@W2 -> C, gather -> A (no relu) ----
    sgemm_t<128, 128, 8, 8, 256><<<gemmBlocks, 256>>>(B, W2, C, N_NODES, 128, 128);
    compute_al_kernel<<<alBlocks, 256>>>(C, a_src2, a_dst2, als, ald);
    gat_gather_kernel<<<gatherBlocks, 256>>>(roff, esrc, als, ald, C, b2, A, 0);

    // ---- SAGE layer 1: fused [y|r] = A @ [wl|wr] -> C, gather-mean -> F ----
    concat_w_kernel<<<(128 * 64 + 255) / 256, 256>>>(s1wl, s1wr, wc, 128);
    sgemm_t<128, 128, 8, 8, 256><<<gemmBlocks, 256>>>(A, wc, C, N_NODES, 128, 128);
    sage_gather_kernel<<<gatherBlocks, 256>>>(roff, esrc, C, s1bl, F,
                                              nullptr, nullptr, nullptr, nullptr, 0);

    // ---- SAGE layer 2 + BN fused ----
    concat_w_kernel<<<(64 * 64 + 255) / 256, 256>>>(s2wl, s2wr, wc, 64);
    sgemm_t<128, 128, 8, 8, 256><<<gemmBlocks, 256>>>(F, wc, B, N_NODES, 64, 128);
    sage_gather_kernel<<<gatherBlocks, 256>>>(roff, esrc, B, s2bl, out,
                                              bng, bnb, bnm, bnv, 1);
}

// round 5
// speedup vs baseline: 1.2772x; 1.2772x over previous
#include <cuda_runtime.h>
#include <cuda_bf16.h>
#include <math.h>
#include <stdint.h>

#define N_NODES 50000
#define E_EDGES 1600000
#define NEG_SLOPE 0.2f
#define BN_EPS 1e-5f

// ---------------- scratch (static device globals; no allocation) ------------
__device__ float g_bufA[(size_t)N_NODES * 128];
__device__ float g_bufB[(size_t)N_NODES * 128];
__device__ float g_bufC[(size_t)N_NODES * 128];
__device__ float g_bufD[(size_t)N_NODES * 64];
__device__ float g_bufE[(size_t)N_NODES * 64];
__device__ float g_bufF[(size_t)N_NODES * 64];
__device__ float g_als[N_NODES * 2];
__device__ float g_ald[N_NODES * 2];
__device__ float g_wc[128 * 128];
__device__ int   g_deg[N_NODES];
__device__ int   g_roff[N_NODES + 1];
__device__ int   g_cur[N_NODES];
__device__ int   g_esrc[E_EDGES];

// ---------------- helpers ----------------------------------------------------
__device__ __forceinline__ float lrelu(float x) {
    return x > 0.0f ? x : NEG_SLOPE * x;
}

__device__ __forceinline__ uint32_t smem_u32(const void* p) {
    return (uint32_t)__cvta_generic_to_shared(p);
}

__device__ __forceinline__ void ldsm_x4(uint32_t* r, uint32_t addr) {
    asm volatile("ldmatrix.sync.aligned.m8n8.x4.shared.b16 {%0,%1,%2,%3}, [%4];"
        : "=r"(r[0]), "=r"(r[1]), "=r"(r[2]), "=r"(r[3]) : "r"(addr));
}

__device__ __forceinline__ void ldsm_x4_t(uint32_t* r, uint32_t addr) {
    asm volatile("ldmatrix.sync.aligned.m8n8.x4.trans.shared.b16 {%0,%1,%2,%3}, [%4];"
        : "=r"(r[0]), "=r"(r[1]), "=r"(r[2]), "=r"(r[3]) : "r"(addr));
}

__device__ __forceinline__ void mma_bf16(float* d, const uint32_t* a,
                                         const uint32_t* b) {
    asm volatile(
        "mma.sync.aligned.m16n8k16.row.col.f32.bf16.bf16.f32 "
        "{%0,%1,%2,%3}, {%4,%5,%6,%7}, {%8,%9}, {%0,%1,%2,%3};"
        : "+f"(d[0]), "+f"(d[1]), "+f"(d[2]), "+f"(d[3])
        : "r"(a[0]), "r"(a[1]), "r"(a[2]), "r"(a[3]), "r"(b[0]), "r"(b[1]));
}

// ---------------- tensor-core GEMM via mma.sync (bf16 x3 split) --------------
// C[M,128] = A[M,K] @ W[K,128]; epilogue splits cols 0-63 -> outA (strideA),
// cols 64-127 -> outB (strideB). Full-precision-ish: A=hi+lo, W=hi+lo,
// acc += Ah*Wh + Ah*Wl + Al*Wh.
#define APAD 24     // A smem row stride (bf16 elems): conflict-free, 16B mult
#define BPAD 136    // W smem row stride

struct MmaSmem {
    __align__(16) __nv_bfloat16 Ahi[128 * APAD];
    __align__(16) __nv_bfloat16 Alo[128 * APAD];
    __align__(16) __nv_bfloat16 Bhi[16 * BPAD];
    __align__(16) __nv_bfloat16 Blo[16 * BPAD];
};

__global__ __launch_bounds__(256, 2) void mma_gemm_kernel(
    const float* __restrict__ A, const float* __restrict__ W,
    float* __restrict__ outA, int strideA,
    float* __restrict__ outB, int strideB,
    int M, int K)
{
    __shared__ MmaSmem sm;

    int tid  = threadIdx.x;
    int wid  = tid >> 5;
    int lane = tid & 31;
    int rowBase = blockIdx.x * 128;

    int warp_m = wid & 1;        // 0..1 -> M offset 0/64
    int warp_n = wid >> 1;       // 0..3 -> N offset 0/32/64/96

    float acc[4][4][4];
    #pragma unroll
    for (int mi = 0; mi < 4; mi++)
        #pragma unroll
        for (int ni = 0; ni < 4; ni++)
            #pragma unroll
            for (int q = 0; q < 4; q++) acc[mi][ni][q] = 0.0f;

    uint32_t a_hi_base = smem_u32(sm.Ahi);
    uint32_t a_lo_base = smem_u32(sm.Alo);
    uint32_t b_hi_base = smem_u32(sm.Bhi);
    uint32_t b_lo_base = smem_u32(sm.Blo);

    // ldmatrix lane address components
    int a_r = (lane & 7) + ((lane >> 3) & 1) * 8;   // row within m16 frag
    int a_c = (lane >> 4) * 8;                      // k offset 0/8
    int b_r = lane & 15;                            // k row
    int b_c = (lane >> 4) * 8;                      // n offset 0/8

    int nchunk = K >> 4;
    for (int c = 0; c < nchunk; c++) {
        int k0 = c << 4;

        // load A chunk [128 x 16] fp32, split to bf16 hi/lo
        float4 av[2];
        int arow[2];
        #pragma unroll
        for (int h = 0; h < 2; h++) {
            int i = tid + h * 256;           // 0..511
            int r = i >> 2, c4 = (i & 3) * 4;
            arow[h] = r * APAD + c4;
            int gr = rowBase + r;
            av[h] = make_float4(0.f, 0.f, 0.f, 0.f);
            if (gr < M) av[h] = *(const float4*)(A + (size_t)gr * K + k0 + c4);
        }
        // load W chunk [16 x 128] fp32
        float4 wv[2];
        int wrow[2];
        #pragma unroll
        for (int h = 0; h < 2; h++) {
            int i = tid + h * 256;
            int r = i >> 5, c4 = (i & 31) * 4;
            wrow[h] = r * BPAD + c4;
            wv[h] = *(const float4*)(W + (size_t)(k0 + r) * 128 + c4);
        }

        __syncthreads();   // previous chunk's ldmatrix done

        #pragma unroll
        for (int h = 0; h < 2; h++) {
            float* vp = (float*)&av[h];
            #pragma unroll
            for (int q = 0; q < 4; q++) {
                __nv_bfloat16 hi = __float2bfloat16(vp[q]);
                sm.Ahi[arow[h] + q] = hi;
                sm.Alo[arow[h] + q] = __float2bfloat16(vp[q] - __bfloat162float(hi));
            }
            float* wp = (float*)&wv[h];
            #pragma unroll
            for (int q = 0; q < 4; q++) {
                __nv_bfloat16 hi = __float2bfloat16(wp[q]);
                sm.Bhi[wrow[h] + q] = hi;
                sm.Blo[wrow[h] + q] = __float2bfloat16(wp[q] - __bfloat162float(hi));
            }
        }
        __syncthreads();

        // B fragments: 2 n-halves x (hi/lo)
        uint32_t bh[2][4], bl[2][4];
        #pragma unroll
        for (int nh = 0; nh < 2; nh++) {
            uint32_t boff = (uint32_t)(b_r * BPAD + warp_n * 32 + nh * 16 + b_c) * 2;
            ldsm_x4_t(bh[nh], b_hi_base + boff);
            ldsm_x4_t(bl[nh], b_lo_base + boff);
        }

        #pragma unroll
        for (int mi = 0; mi < 4; mi++) {
            uint32_t aoff = (uint32_t)((warp_m * 64 + mi * 16 + a_r) * APAD + a_c) * 2;
            uint32_t ah[4], al[4];
            ldsm_x4(ah, a_hi_base + aoff);
            ldsm_x4(al, a_lo_base + aoff);
            #pragma unroll
            for (int ni = 0; ni < 4; ni++) {
                const uint32_t* bhp = &bh[ni >> 1][(ni & 1) * 2];
                const uint32_t* blp = &bl[ni >> 1][(ni & 1) * 2];
                mma_bf16(acc[mi][ni], ah, bhp);
                mma_bf16(acc[mi][ni], ah, blp);
                mma_bf16(acc[mi][ni], al, bhp);
            }
        }
    }

    // epilogue: split write
    int g = lane >> 2, tig = lane & 3;
    #pragma unroll
    for (int mi = 0; mi < 4; mi++) {
        int row = rowBase + warp_m * 64 + mi * 16 + g;
        #pragma unroll
        for (int ni = 0; ni < 4; ni++) {
            int col = warp_n * 32 + ni * 8 + tig * 2;
            float* p0;
            if (col < 64) p0 = outA + (size_t)row * strideA + col;
            else          p0 = outB + (size_t)row * strideB + (col - 64);
            size_t rs = (col < 64) ? (size_t)strideA : (size_t)strideB;
            if (row < M)
                *(float2*)p0 = make_float2(acc[mi][ni][0], acc[mi][ni][1]);
            if (row + 8 < M)
                *(float2*)(p0 + 8 * rs) = make_float2(acc[mi][ni][2], acc[mi][ni][3]);
        }
    }
}

// ---------------- CSR build ---------------------------------------------------
__global__ void hist_kernel(const int* __restrict__ dst, int* __restrict__ deg)
{
    int e = blockIdx.x * blockDim.x + threadIdx.x;
    if (e < E_EDGES) atomicAdd(&deg[dst[e]], 1);
}

__global__ __launch_bounds__(1024) void scan_kernel(
    const int* __restrict__ deg, int* __restrict__ roff, int* __restrict__ cur)
{
    __shared__ int part[1024];
    const int CH = (N_NODES + 1023) / 1024;
    int t = threadIdx.x;
    int base = t * CH;
    int sum = 0;
    for (int i = 0; i < CH; i++) {
        int idx = base + i;
        if (idx < N_NODES) sum += deg[idx];
    }
    part[t] = sum;
    __syncthreads();
    for (int off = 1; off < 1024; off <<= 1) {
        int v = (t >= off) ? part[t - off] : 0;
        __syncthreads();
        part[t] += v;
        __syncthreads();
    }
    int run = part[t] - sum;
    for (int i = 0; i < CH; i++) {
        int idx = base + i;
        if (idx < N_NODES) {
            roff[idx] = run;
            cur[idx]  = run;
            run += deg[idx];
        }
    }
    if (t == 1023) roff[N_NODES] = run;
}

__global__ void scatter_kernel(const int* __restrict__ src,
                               const int* __restrict__ dst,
                               int* __restrict__ cur, int* __restrict__ esrc)
{
    int e = blockIdx.x * blockDim.x + threadIdx.x;
    if (e >= E_EDGES) return;
    int d = dst[e];
    int p = atomicAdd(&cur[d], 1);
    esrc[p] = src[e];
}

// ---------------- GAT attention-logit precompute -----------------------------
__global__ void compute_al_kernel(
    const float* __restrict__ h, const float* __restrict__ a_src,
    const float* __restrict__ a_dst, float* __restrict__ als,
    float* __restrict__ ald)
{
    int warp = (blockIdx.x * blockDim.x + threadIdx.x) >> 5;
    int lane = threadIdx.x & 31;
    if (warp >= N_NODES) return;

    float4 hv = *(const float4*)(h + (size_t)warp * 128 + lane * 4);
    float4 as = *(const float4*)(a_src + lane * 4);
    float4 ad = *(const float4*)(a_dst + lane * 4);
    float ss = hv.x * as.x + hv.y * as.y + hv.z * as.z + hv.w * as.w;
    float sd = hv.x * ad.x + hv.y * ad.y + hv.z * ad.z + hv.w * ad.w;
    #pragma unroll
    for (int o = 8; o; o >>= 1) {
        ss += __shfl_xor_sync(0xffffffffu, ss, o);
        sd += __shfl_xor_sync(0xffffffffu, sd, o);
    }
    if (lane == 0)  { als[warp * 2 + 0] = ss; ald[warp * 2 + 0] = sd; }
    if (lane == 16) { als[warp * 2 + 1] = ss; ald[warp * 2 + 1] = sd; }
}

// ---------------- fused GAT gather (round-2 proven version) ------------------
__global__ __launch_bounds__(256) void gat_gather_kernel(
    const int* __restrict__ roff, const int* __restrict__ esrc,
    const float* __restrict__ als, const float* __restrict__ ald,
    const float* __restrict__ h, const float* __restrict__ bias,
    float* __restrict__ out, int relu)
{
    int d = (blockIdx.x * blockDim.x + threadIdx.x) >> 5;
    int lane = threadIdx.x & 31;
    if (d >= N_NODES) return;

    float2 ad = *(const float2*)(ald + 2 * d);
    float2 a_self = *(const float2*)(als + 2 * d);
    float es0 = lrelu(a_self.x + ad.x);
    float es1 = lrelu(a_self.y + ad.y);

    int beg = roff[d], end = roff[d + 1];

    // pass 1: max
    float m0 = es0, m1 = es1;
    for (int i = beg + lane; i < end; i += 32) {
        int s = __ldg(esrc + i);
        float2 a = *(const float2*)(als + 2 * s);
        m0 = fmaxf(m0, lrelu(a.x + ad.x));
        m1 = fmaxf(m1, lrelu(a.y + ad.y));
    }
    #pragma unroll
    for (int o = 16; o; o >>= 1) {
        m0 = fmaxf(m0, __shfl_xor_sync(0xffffffffu, m0, o));
        m1 = fmaxf(m1, __shfl_xor_sync(0xffffffffu, m1, o));
    }

    // pass 2: exp-sum
    float s0 = 0.0f, s1 = 0.0f;
    for (int i = beg + lane; i < end; i += 32) {
        int s = __ldg(esrc + i);
        float2 a = *(const float2*)(als + 2 * s);
        s0 += expf(lrelu(a.x + ad.x) - m0);
        s1 += expf(lrelu(a.y + ad.y) - m1);
    }
    #pragma unroll
    for (int o = 16; o; o >>= 1) {
        s0 += __shfl_xor_sync(0xffffffffu, s0, o);
        s1 += __shfl_xor_sync(0xffffffffu, s1, o);
    }
    s0 += expf(es0 - m0);
    s1 += expf(es1 - m1);
    float inv0 = 1.0f / s0, inv1 = 1.0f / s1;

    // pass 3: weighted accumulation
    float mh   = (lane < 16) ? m0 : m1;
    float invh = (lane < 16) ? inv0 : inv1;
    float adh  = (lane < 16) ? ad.x : ad.y;
    float esh  = (lane < 16) ? es0 : es1;

    float alpha_self = expf(esh - mh) * invh;
    float4 hv = *(const float4*)(h + (size_t)d * 128 + lane * 4);
    float4 acc;
    acc.x = alpha_self * hv.x;
    acc.y = alpha_self * hv.y;
    acc.z = alpha_self * hv.z;
    acc.w = alpha_self * hv.w;

    for (int i = beg; i < end; i++) {
        int s = __ldg(esrc + i);
        float a = __ldg(als + 2 * s + (lane < 16 ? 0 : 1));
        float alpha = expf(lrelu(a + adh) - mh) * invh;
        float4 v = *(const float4*)(h + (size_t)s * 128 + lane * 4);
        acc.x = fmaf(alpha, v.x, acc.x);
        acc.y = fmaf(alpha, v.y, acc.y);
        acc.z = fmaf(alpha, v.z, acc.z);
        acc.w = fmaf(alpha, v.w, acc.w);
    }

    float4 b = *(const float4*)(bias + lane * 4);
    acc.x += b.x; acc.y += b.y; acc.z += b.z; acc.w += b.w;
    if (relu) {
        acc.x = fmaxf(acc.x, 0.0f);
        acc.y = fmaxf(acc.y, 0.0f);
        acc.z = fmaxf(acc.z, 0.0f);
        acc.w = fmaxf(acc.w, 0.0f);
    }
    *(float4*)(out + (size_t)d * 128 + lane * 4) = acc;
}

// ---------------- weight concat for fused SAGE GEMM --------------------------
__global__ void concat_w_kernel(const float* __restrict__ wl,
                                const float* __restrict__ wr,
                                float* __restrict__ wc, int K)
{
    int i = blockIdx.x * blockDim.x + threadIdx.x;
    if (i >= K * 64) return;
    int k = i >> 6, c = i & 63;
    wc[k * 128 + c]      = wl[i];
    wc[k * 128 + 64 + c] = wr[i];
}

// ---------------- fused SAGE gather (round-2 proven version) -----------------
__global__ __launch_bounds__(256) void sage_gather_kernel(
    const int* __restrict__ roff, const int* __restrict__ esrc,
    const float* __restrict__ y, const float* __restrict__ bl,
    const float* __restrict__ r, float* __restrict__ out,
    const float* __restrict__ gamma, const float* __restrict__ beta,
    const float* __restrict__ mean, const float* __restrict__ var,
    int do_bn)
{
    int d = (blockIdx.x * blockDim.x + threadIdx.x) >> 5;
    int lane = threadIdx.x & 31;
    if (d >= N_NODES) return;

    int beg = roff[d], end = roff[d + 1];
    float ax = 0.0f, ay = 0.0f;
    for (int i = beg; i < end; i++) {
        int s = __ldg(esrc + i);
        float2 v = *(const float2*)(y + (size_t)s * 64 + lane * 2);
        ax += v.x;
        ay += v.y;
    }
    float invc = 1.0f / fmaxf((float)(end - beg), 1.0f);
    int c = lane * 2;
    float2 bb = *(const float2*)(bl + c);
    float2 rr = *(const float2*)(r + (size_t)d * 64 + c);
    float vx = fmaxf(ax * invc + bb.x + rr.x, 0.0f);
    float vy = fmaxf(ay * invc + bb.y + rr.y, 0.0f);
    if (do_bn) {
        float sx = gamma[c]     * rsqrtf(var[c]     + BN_EPS);
        float sy = gamma[c + 1] * rsqrtf(var[c + 1] + BN_EPS);
        vx = (vx - mean[c])     * sx + beta[c];
        vy = (vy - mean[c + 1]) * sy + beta[c + 1];
    }
    *(float2*)(out + (size_t)d * 64 + c) = make_float2(vx, vy);
}

// ---------------- host orchestration -----------------------------------------
extern "C" void kernel_launch(void* const* d_in, const int* in_sizes, int n_in,
                              void* d_out, int out_size)
{
    const float* x      = (const float*)d_in[0];
    const int*   ei     = (const int*)d_in[1];
    const float* W1     = (const float*)d_in[2];
    const float* a_src1 = (const float*)d_in[3];
    const float* a_dst1 = (const float*)d_in[4];
    const float* b1     = (const float*)d_in[5];
    const float* W2     = (const float*)d_in[6];
    const float* a_src2 = (const float*)d_in[7];
    const float* a_dst2 = (const float*)d_in[8];
    const float* b2     = (const float*)d_in[9];
    const float* s1wl   = (const float*)d_in[10];
    const float* s1bl   = (const float*)d_in[11];
    const float* s1wr   = (const float*)d_in[12];
    const float* s2wl   = (const float*)d_in[13];
    const float* s2bl   = (const float*)d_in[14];
    const float* s2wr   = (const float*)d_in[15];
    const float* bng    = (const float*)d_in[16];
    const float* bnb    = (const float*)d_in[17];
    const float* bnm    = (const float*)d_in[18];
    const float* bnv    = (const float*)d_in[19];
    float* out = (float*)d_out;

    const int* src = ei;
    const int* dst = ei + E_EDGES;

    float *A, *B, *C, *D, *Ebuf, *F, *als, *ald, *wc;
    int *deg, *roff, *cur, *esrc;
    cudaGetSymbolAddress((void**)&A,    g_bufA);
    cudaGetSymbolAddress((void**)&B,    g_bufB);
    cudaGetSymbolAddress((void**)&C,    g_bufC);
    cudaGetSymbolAddress((void**)&D,    g_bufD);
    cudaGetSymbolAddress((void**)&Ebuf, g_bufE);
    cudaGetSymbolAddress((void**)&F,    g_bufF);
    cudaGetSymbolAddress((void**)&als,  g_als);
    cudaGetSymbolAddress((void**)&ald,  g_ald);
    cudaGetSymbolAddress((void**)&wc,   g_wc);
    cudaGetSymbolAddress((void**)&deg,  g_deg);
    cudaGetSymbolAddress((void**)&roff, g_roff);
    cudaGetSymbolAddress((void**)&cur,  g_cur);
    cudaGetSymbolAddress((void**)&esrc, g_esrc);

    // ---- CSR build (by dst) ----
    cudaMemsetAsync(deg, 0, N_NODES * sizeof(int), 0);
    hist_kernel<<<(E_EDGES + 255) / 256, 256>>>(dst, deg);
    scan_kernel<<<1, 1024>>>(deg, roff, cur);
    scatter_kernel<<<(E_EDGES + 255) / 256, 256>>>(src, dst, cur, esrc);

    int gemmBlocks   = (N_NODES + 127) / 128;
    int gatherBlocks = (N_NODES * 32 + 255) / 256;
    int alBlocks     = (N_NODES + 7) / 8;

    // ---- GAT layer 1: h1 = x@W1 -> A (128-wide), gather -> B (relu) ----
    mma_gemm_kernel<<<gemmBlocks, 256>>>(x, W1, A, 128, A + 64, 128,
                                         N_NODES, 256);
    compute_al_kernel<<<alBlocks, 256>>>(A, a_src1, a_dst1, als, ald);
    gat_gather_kernel<<<gatherBlocks, 256>>>(roff, esrc, als, ald, A, b1, B, 1);

    // ---- GAT layer 2: h2 = B@W2 -> C, gather -> A (no relu) ----
    mma_gemm_kernel<<<gemmBlocks, 256>>>(B, W2, C, 128, C + 64, 128,
                                         N_NODES, 128);
    compute_al_kernel<<<alBlocks, 256>>>(C, a_src2, a_dst2, als, ald);
    gat_gather_kernel<<<gatherBlocks, 256>>>(roff, esrc, als, ald, C, b2, A, 0);

    // ---- SAGE layer 1: one GEMM -> y1 (D, dense 64) and r1 (Ebuf, dense 64) ----
    concat_w_kernel<<<(128 * 64 + 255) / 256, 256>>>(s1wl, s1wr, wc, 128);
    mma_gemm_kernel<<<gemmBlocks, 256>>>(A, wc, D, 64, Ebuf, 64, N_NODES, 128);
    sage_gather_kernel<<<gatherBlocks, 256>>>(roff, esrc, D, s1bl, Ebuf, F,
                                              nullptr, nullptr, nullptr, nullptr, 0);

    // ---- SAGE layer 2 + BN fused ----
    concat_w_kernel<<<(64 * 64 + 255) / 256, 256>>>(s2wl, s2wr, wc, 64);
    mma_gemm_kernel<<<gemmBlocks, 256>>>(F, wc, D, 64, Ebuf, 64, N_NODES, 64);
    sage_gather_kernel<<<gatherBlocks, 256>>>(roff, esrc, D, s2bl, Ebuf, out,
                                              bng, bnb, bnm, bnv, 1);
}

// round 6
// speedup vs baseline: 1.3511x; 1.0579x over previous
#include <cuda_runtime.h>
#include <cuda_bf16.h>
#include <math.h>
#include <stdint.h>

#define N_NODES 50000
#define E_EDGES 1600000
#define NEG_SLOPE 0.2f
#define BN_EPS 1e-5f

// ---------------- scratch (static device globals; no allocation) ------------
__device__ float g_bufA[(size_t)N_NODES * 128];
__device__ float g_bufB[(size_t)N_NODES * 128];
__device__ float g_bufC[(size_t)N_NODES * 128];
__device__ float g_bufD[(size_t)N_NODES * 64];
__device__ float g_bufE[(size_t)N_NODES * 64];
__device__ float g_bufF[(size_t)N_NODES * 64];
__device__ float g_als[N_NODES * 2];
__device__ float g_ald[N_NODES * 2];
__device__ float g_wc[128 * 128];
__device__ int   g_deg[N_NODES];
__device__ int   g_roff[N_NODES + 1];
__device__ int   g_cur[N_NODES];
__device__ int   g_esrc[E_EDGES];

// ---------------- helpers ----------------------------------------------------
__device__ __forceinline__ float lrelu(float x) {
    return x > 0.0f ? x : NEG_SLOPE * x;
}

__device__ __forceinline__ uint32_t smem_u32(const void* p) {
    return (uint32_t)__cvta_generic_to_shared(p);
}

__device__ __forceinline__ void ldsm_x4(uint32_t* r, uint32_t addr) {
    asm volatile("ldmatrix.sync.aligned.m8n8.x4.shared.b16 {%0,%1,%2,%3}, [%4];"
        : "=r"(r[0]), "=r"(r[1]), "=r"(r[2]), "=r"(r[3]) : "r"(addr));
}

__device__ __forceinline__ void ldsm_x4_t(uint32_t* r, uint32_t addr) {
    asm volatile("ldmatrix.sync.aligned.m8n8.x4.trans.shared.b16 {%0,%1,%2,%3}, [%4];"
        : "=r"(r[0]), "=r"(r[1]), "=r"(r[2]), "=r"(r[3]) : "r"(addr));
}

__device__ __forceinline__ void mma_bf16(float* d, const uint32_t* a,
                                         const uint32_t* b) {
    asm volatile(
        "mma.sync.aligned.m16n8k16.row.col.f32.bf16.bf16.f32 "
        "{%0,%1,%2,%3}, {%4,%5,%6,%7}, {%8,%9}, {%0,%1,%2,%3};"
        : "+f"(d[0]), "+f"(d[1]), "+f"(d[2]), "+f"(d[3])
        : "r"(a[0]), "r"(a[1]), "r"(a[2]), "r"(a[3]), "r"(b[0]), "r"(b[1]));
}

// ---------------- tensor-core GEMM via mma.sync (bf16 x3 split) --------------
// Software-pipelined: chunk c+1 global loads issue before chunk c's MMAs.
#define APAD 24
#define BPAD 136

struct MmaSmem {
    __align__(16) __nv_bfloat16 Ahi[128 * APAD];
    __align__(16) __nv_bfloat16 Alo[128 * APAD];
    __align__(16) __nv_bfloat16 Bhi[16 * BPAD];
    __align__(16) __nv_bfloat16 Blo[16 * BPAD];
};

__global__ __launch_bounds__(256, 2) void mma_gemm_kernel(
    const float* __restrict__ A, const float* __restrict__ W,
    float* __restrict__ outA, int strideA,
    float* __restrict__ outB, int strideB,
    int M, int K)
{
    __shared__ MmaSmem sm;

    int tid  = threadIdx.x;
    int wid  = tid >> 5;
    int lane = tid & 31;
    int rowBase = blockIdx.x * 128;

    int warp_m = wid & 1;
    int warp_n = wid >> 1;

    float acc[4][4][4];
    #pragma unroll
    for (int mi = 0; mi < 4; mi++)
        #pragma unroll
        for (int ni = 0; ni < 4; ni++)
            #pragma unroll
            for (int q = 0; q < 4; q++) acc[mi][ni][q] = 0.0f;

    uint32_t a_hi_base = smem_u32(sm.Ahi);
    uint32_t a_lo_base = smem_u32(sm.Alo);
    uint32_t b_hi_base = smem_u32(sm.Bhi);
    uint32_t b_lo_base = smem_u32(sm.Blo);

    int a_r = (lane & 7) + ((lane >> 3) & 1) * 8;
    int a_c = (lane >> 4) * 8;
    int b_r = lane & 15;
    int b_c = (lane >> 4) * 8;

    // per-thread load geometry (k-independent)
    int aR[2], aC[2], wR[2], wC[2], arow[2], wrow[2];
    bool aok[2];
    #pragma unroll
    for (int h = 0; h < 2; h++) {
        int i = tid + h * 256;
        aR[h] = i >> 2;  aC[h] = (i & 3) * 4;
        wR[h] = i >> 5;  wC[h] = (i & 31) * 4;
        arow[h] = aR[h] * APAD + aC[h];
        wrow[h] = wR[h] * BPAD + wC[h];
        aok[h]  = (rowBase + aR[h]) < M;
    }

    float4 av[2], wv[2];
    // prologue: load chunk 0
    #pragma unroll
    for (int h = 0; h < 2; h++) {
        av[h] = make_float4(0.f, 0.f, 0.f, 0.f);
        if (aok[h]) av[h] = *(const float4*)(A + (size_t)(rowBase + aR[h]) * K + aC[h]);
        wv[h] = *(const float4*)(W + (size_t)wR[h] * 128 + wC[h]);
    }

    int nchunk = K >> 4;
    for (int c = 0; c < nchunk; c++) {
        __syncthreads();    // ldmatrix consumers of previous chunk done

        // convert + store current chunk
        #pragma unroll
        for (int h = 0; h < 2; h++) {
            float* vp = (float*)&av[h];
            #pragma unroll
            for (int q = 0; q < 4; q++) {
                __nv_bfloat16 hi = __float2bfloat16(vp[q]);
                sm.Ahi[arow[h] + q] = hi;
                sm.Alo[arow[h] + q] = __float2bfloat16(vp[q] - __bfloat162float(hi));
            }
            float* wp = (float*)&wv[h];
            #pragma unroll
            for (int q = 0; q < 4; q++) {
                __nv_bfloat16 hi = __float2bfloat16(wp[q]);
                sm.Bhi[wrow[h] + q] = hi;
                sm.Blo[wrow[h] + q] = __float2bfloat16(wp[q] - __bfloat162float(hi));
            }
        }
        __syncthreads();

        // prefetch chunk c+1 (LDG latency hidden under MMAs below)
        if (c + 1 < nchunk) {
            int k0n = (c + 1) << 4;
            #pragma unroll
            for (int h = 0; h < 2; h++) {
                av[h] = make_float4(0.f, 0.f, 0.f, 0.f);
                if (aok[h])
                    av[h] = *(const float4*)(A + (size_t)(rowBase + aR[h]) * K + k0n + aC[h]);
                wv[h] = *(const float4*)(W + (size_t)(k0n + wR[h]) * 128 + wC[h]);
            }
        }

        // MMA block for current chunk
        uint32_t bh[2][4], bl[2][4];
        #pragma unroll
        for (int nh = 0; nh < 2; nh++) {
            uint32_t boff = (uint32_t)(b_r * BPAD + warp_n * 32 + nh * 16 + b_c) * 2;
            ldsm_x4_t(bh[nh], b_hi_base + boff);
            ldsm_x4_t(bl[nh], b_lo_base + boff);
        }
        #pragma unroll
        for (int mi = 0; mi < 4; mi++) {
            uint32_t aoff = (uint32_t)((warp_m * 64 + mi * 16 + a_r) * APAD + a_c) * 2;
            uint32_t ah[4], al[4];
            ldsm_x4(ah, a_hi_base + aoff);
            ldsm_x4(al, a_lo_base + aoff);
            #pragma unroll
            for (int ni = 0; ni < 4; ni++) {
                const uint32_t* bhp = &bh[ni >> 1][(ni & 1) * 2];
                const uint32_t* blp = &bl[ni >> 1][(ni & 1) * 2];
                mma_bf16(acc[mi][ni], ah, bhp);
                mma_bf16(acc[mi][ni], ah, blp);
                mma_bf16(acc[mi][ni], al, bhp);
            }
        }
    }

    // epilogue: split write
    int g = lane >> 2, tig = lane & 3;
    #pragma unroll
    for (int mi = 0; mi < 4; mi++) {
        int row = rowBase + warp_m * 64 + mi * 16 + g;
        #pragma unroll
        for (int ni = 0; ni < 4; ni++) {
            int col = warp_n * 32 + ni * 8 + tig * 2;
            float* p0;
            if (col < 64) p0 = outA + (size_t)row * strideA + col;
            else          p0 = outB + (size_t)row * strideB + (col - 64);
            size_t rs = (col < 64) ? (size_t)strideA : (size_t)strideB;
            if (row < M)
                *(float2*)p0 = make_float2(acc[mi][ni][0], acc[mi][ni][1]);
            if (row + 8 < M)
                *(float2*)(p0 + 8 * rs) = make_float2(acc[mi][ni][2], acc[mi][ni][3]);
        }
    }
}

// ---------------- CSR build ---------------------------------------------------
__global__ void hist_kernel(const int* __restrict__ dst, int* __restrict__ deg)
{
    int e = blockIdx.x * blockDim.x + threadIdx.x;
    if (e < E_EDGES) atomicAdd(&deg[dst[e]], 1);
}

__global__ __launch_bounds__(1024) void scan_kernel(
    const int* __restrict__ deg, int* __restrict__ roff, int* __restrict__ cur)
{
    __shared__ int part[1024];
    const int CH = (N_NODES + 1023) / 1024;
    int t = threadIdx.x;
    int base = t * CH;
    int sum = 0;
    for (int i = 0; i < CH; i++) {
        int idx = base + i;
        if (idx < N_NODES) sum += deg[idx];
    }
    part[t] = sum;
    __syncthreads();
    for (int off = 1; off < 1024; off <<= 1) {
        int v = (t >= off) ? part[t - off] : 0;
        __syncthreads();
        part[t] += v;
        __syncthreads();
    }
    int run = part[t] - sum;
    for (int i = 0; i < CH; i++) {
        int idx = base + i;
        if (idx < N_NODES) {
            roff[idx] = run;
            cur[idx]  = run;
            run += deg[idx];
        }
    }
    if (t == 1023) roff[N_NODES] = run;
}

__global__ void scatter_kernel(const int* __restrict__ src,
                               const int* __restrict__ dst,
                               int* __restrict__ cur, int* __restrict__ esrc)
{
    int e = blockIdx.x * blockDim.x + threadIdx.x;
    if (e >= E_EDGES) return;
    int d = dst[e];
    int p = atomicAdd(&cur[d], 1);
    esrc[p] = src[e];
}

// ---------------- GAT attention-logit precompute -----------------------------
__global__ void compute_al_kernel(
    const float* __restrict__ h, const float* __restrict__ a_src,
    const float* __restrict__ a_dst, float* __restrict__ als,
    float* __restrict__ ald)
{
    int warp = (blockIdx.x * blockDim.x + threadIdx.x) >> 5;
    int lane = threadIdx.x & 31;
    if (warp >= N_NODES) return;

    float4 hv = *(const float4*)(h + (size_t)warp * 128 + lane * 4);
    float4 as = *(const float4*)(a_src + lane * 4);
    float4 ad = *(const float4*)(a_dst + lane * 4);
    float ss = hv.x * as.x + hv.y * as.y + hv.z * as.z + hv.w * as.w;
    float sd = hv.x * ad.x + hv.y * ad.y + hv.z * ad.z + hv.w * ad.w;
    #pragma unroll
    for (int o = 8; o; o >>= 1) {
        ss += __shfl_xor_sync(0xffffffffu, ss, o);
        sd += __shfl_xor_sync(0xffffffffu, sd, o);
    }
    if (lane == 0)  { als[warp * 2 + 0] = ss; ald[warp * 2 + 0] = sd; }
    if (lane == 16) { als[warp * 2 + 1] = ss; ald[warp * 2 + 1] = sd; }
}

// ---------------- fused GAT gather: single pass, 4-way unrolled ---------------
// one warp per dst node; lane owns 4 feature cols. Unnormalized exp weights
// accumulated with features; normalize at end (logits O(10), exp-safe).
__global__ __launch_bounds__(256) void gat_gather_kernel(
    const int* __restrict__ roff, const int* __restrict__ esrc,
    const float* __restrict__ als, const float* __restrict__ ald,
    const float* __restrict__ h, const float* __restrict__ bias,
    float* __restrict__ out, int relu)
{
    int d = (blockIdx.x * blockDim.x + threadIdx.x) >> 5;
    int lane = threadIdx.x & 31;
    if (d >= N_NODES) return;

    float2 ad = *(const float2*)(ald + 2 * d);
    float2 a_self = *(const float2*)(als + 2 * d);
    int head = (lane >= 16);

    float w_self0 = expf(lrelu(a_self.x + ad.x));
    float w_self1 = expf(lrelu(a_self.y + ad.y));
    float s0 = w_self0, s1 = w_self1;
    float wsh = head ? w_self1 : w_self0;

    float4 hv = *(const float4*)(h + (size_t)d * 128 + lane * 4);
    float4 acc;
    acc.x = wsh * hv.x;
    acc.y = wsh * hv.y;
    acc.z = wsh * hv.z;
    acc.w = wsh * hv.w;

    int beg = roff[d], end = roff[d + 1];
    int i = beg;
    for (; i + 4 <= end; i += 4) {
        int sI[4];
        float2 aI[4];
        float4 vI[4];
        #pragma unroll
        for (int j = 0; j < 4; j++) sI[j] = __ldg(esrc + i + j);
        #pragma unroll
        for (int j = 0; j < 4; j++) aI[j] = *(const float2*)(als + 2 * sI[j]);
        #pragma unroll
        for (int j = 0; j < 4; j++)
            vI[j] = *(const float4*)(h + (size_t)sI[j] * 128 + lane * 4);
        #pragma unroll
        for (int j = 0; j < 4; j++) {
            float w0 = expf(lrelu(aI[j].x + ad.x));
            float w1 = expf(lrelu(aI[j].y + ad.y));
            s0 += w0;
            s1 += w1;
            float wh = head ? w1 : w0;
            acc.x = fmaf(wh, vI[j].x, acc.x);
            acc.y = fmaf(wh, vI[j].y, acc.y);
            acc.z = fmaf(wh, vI[j].z, acc.z);
            acc.w = fmaf(wh, vI[j].w, acc.w);
        }
    }
    for (; i < end; i++) {
        int s = __ldg(esrc + i);
        float2 a = *(const float2*)(als + 2 * s);
        float4 v = *(const float4*)(h + (size_t)s * 128 + lane * 4);
        float w0 = expf(lrelu(a.x + ad.x));
        float w1 = expf(lrelu(a.y + ad.y));
        s0 += w0;
        s1 += w1;
        float wh = head ? w1 : w0;
        acc.x = fmaf(wh, v.x, acc.x);
        acc.y = fmaf(wh, v.y, acc.y);
        acc.z = fmaf(wh, v.z, acc.z);
        acc.w = fmaf(wh, v.w, acc.w);
    }

    float inv = 1.0f / (head ? s1 : s0);
    float4 b = *(const float4*)(bias + lane * 4);
    acc.x = fmaf(acc.x, inv, b.x);
    acc.y = fmaf(acc.y, inv, b.y);
    acc.z = fmaf(acc.z, inv, b.z);
    acc.w = fmaf(acc.w, inv, b.w);
    if (relu) {
        acc.x = fmaxf(acc.x, 0.0f);
        acc.y = fmaxf(acc.y, 0.0f);
        acc.z = fmaxf(acc.z, 0.0f);
        acc.w = fmaxf(acc.w, 0.0f);
    }
    *(float4*)(out + (size_t)d * 128 + lane * 4) = acc;
}

// ---------------- weight concat for fused SAGE GEMM --------------------------
__global__ void concat_w_kernel(const float* __restrict__ wl,
                                const float* __restrict__ wr,
                                float* __restrict__ wc, int K)
{
    int i = blockIdx.x * blockDim.x + threadIdx.x;
    if (i >= K * 64) return;
    int k = i >> 6, c = i & 63;
    wc[k * 128 + c]      = wl[i];
    wc[k * 128 + 64 + c] = wr[i];
}

// ---------------- fused SAGE gather (mean + bias + root + relu [+ BN]) -------
__global__ __launch_bounds__(256) void sage_gather_kernel(
    const int* __restrict__ roff, const int* __restrict__ esrc,
    const float* __restrict__ y, const float* __restrict__ bl,
    const float* __restrict__ r, float* __restrict__ out,
    const float* __restrict__ gamma, const float* __restrict__ beta,
    const float* __restrict__ mean, const float* __restrict__ var,
    int do_bn)
{
    int d = (blockIdx.x * blockDim.x + threadIdx.x) >> 5;
    int lane = threadIdx.x & 31;
    if (d >= N_NODES) return;

    int beg = roff[d], end = roff[d + 1];
    float ax = 0.0f, ay = 0.0f;
    int i = beg;
    for (; i + 4 <= end; i += 4) {
        int sI[4];
        float2 vI[4];
        #pragma unroll
        for (int j = 0; j < 4; j++) sI[j] = __ldg(esrc + i + j);
        #pragma unroll
        for (int j = 0; j < 4; j++)
            vI[j] = *(const float2*)(y + (size_t)sI[j] * 64 + lane * 2);
        #pragma unroll
        for (int j = 0; j < 4; j++) { ax += vI[j].x; ay += vI[j].y; }
    }
    for (; i < end; i++) {
        int s = __ldg(esrc + i);
        float2 v = *(const float2*)(y + (size_t)s * 64 + lane * 2);
        ax += v.x;
        ay += v.y;
    }
    float invc = 1.0f / fmaxf((float)(end - beg), 1.0f);
    int c = lane * 2;
    float2 bb = *(const float2*)(bl + c);
    float2 rr = *(const float2*)(r + (size_t)d * 64 + c);
    float vx = fmaxf(ax * invc + bb.x + rr.x, 0.0f);
    float vy = fmaxf(ay * invc + bb.y + rr.y, 0.0f);
    if (do_bn) {
        float sx = gamma[c]     * rsqrtf(var[c]     + BN_EPS);
        float sy = gamma[c + 1] * rsqrtf(var[c + 1] + BN_EPS);
        vx = (vx - mean[c])     * sx + beta[c];
        vy = (vy - mean[c + 1]) * sy + beta[c + 1];
    }
    *(float2*)(out + (size_t)d * 64 + c) = make_float2(vx, vy);
}

// ---------------- host orchestration -----------------------------------------
extern "C" void kernel_launch(void* const* d_in, const int* in_sizes, int n_in,
                              void* d_out, int out_size)
{
    const float* x      = (const float*)d_in[0];
    const int*   ei     = (const int*)d_in[1];
    const float* W1     = (const float*)d_in[2];
    const float* a_src1 = (const float*)d_in[3];
    const float* a_dst1 = (const float*)d_in[4];
    const float* b1     = (const float*)d_in[5];
    const float* W2     = (const float*)d_in[6];
    const float* a_src2 = (const float*)d_in[7];
    const float* a_dst2 = (const float*)d_in[8];
    const float* b2     = (const float*)d_in[9];
    const float* s1wl   = (const float*)d_in[10];
    const float* s1bl   = (const float*)d_in[11];
    const float* s1wr   = (const float*)d_in[12];
    const float* s2wl   = (const float*)d_in[13];
    const float* s2bl   = (const float*)d_in[14];
    const float* s2wr   = (const float*)d_in[15];
    const float* bng    = (const float*)d_in[16];
    const float* bnb    = (const float*)d_in[17];
    const float* bnm    = (const float*)d_in[18];
    const float* bnv    = (const float*)d_in[19];
    float* out = (float*)d_out;

    const int* src = ei;
    const int* dst = ei + E_EDGES;

    float *A, *B, *C, *D, *Ebuf, *F, *als, *ald, *wc;
    int *deg, *roff, *cur, *esrc;
    cudaGetSymbolAddress((void**)&A,    g_bufA);
    cudaGetSymbolAddress((void**)&B,    g_bufB);
    cudaGetSymbolAddress((void**)&C,    g_bufC);
    cudaGetSymbolAddress((void**)&D,    g_bufD);
    cudaGetSymbolAddress((void**)&Ebuf, g_bufE);
    cudaGetSymbolAddress((void**)&F,    g_bufF);
    cudaGetSymbolAddress((void**)&als,  g_als);
    cudaGetSymbolAddress((void**)&ald,  g_ald);
    cudaGetSymbolAddress((void**)&wc,   g_wc);
    cudaGetSymbolAddress((void**)&deg,  g_deg);
    cudaGetSymbolAddress((void**)&roff, g_roff);
    cudaGetSymbolAddress((void**)&cur,  g_cur);
    cudaGetSymbolAddress((void**)&esrc, g_esrc);

    // ---- CSR build (by dst) ----
    cudaMemsetAsync(deg, 0, N_NODES * sizeof(int), 0);
    hist_kernel<<<(E_EDGES + 255) / 256, 256>>>(dst, deg);
    scan_kernel<<<1, 1024>>>(deg, roff, cur);
    scatter_kernel<<<(E_EDGES + 255) / 256, 256>>>(src, dst, cur, esrc);

    int gemmBlocks   = (N_NODES + 127) / 128;
    int gatherBlocks = (N_NODES * 32 + 255) / 256;
    int alBlocks     = (N_NODES + 7) / 8;

    // ---- GAT layer 1: h1 = x@W1 -> A (128-wide), gather -> B (relu) ----
    mma_gemm_kernel<<<gemmBlocks, 256>>>(x, W1, A, 128, A + 64, 128,
                                         N_NODES, 256);
    compute_al_kernel<<<alBlocks, 256>>>(A, a_src1, a_dst1, als, ald);
    gat_gather_kernel<<<gatherBlocks, 256>>>(roff, esrc, als, ald, A, b1, B, 1);

    // ---- GAT layer 2: h2 = B@W2 -> C, gather -> A (no relu) ----
    mma_gemm_kernel<<<gemmBlocks, 256>>>(B, W2, C, 128, C + 64, 128,
                                         N_NODES, 128);
    compute_al_kernel<<<alBlocks, 256>>>(C, a_src2, a_dst2, als, ald);
    gat_gather_kernel<<<gatherBlocks, 256>>>(roff, esrc, als, ald, C, b2, A, 0);

    // ---- SAGE layer 1: one GEMM -> y1 (D, dense 64) and r1 (Ebuf, dense 64) ----
    concat_w_kernel<<<(128 * 64 + 255) / 256, 256>>>(s1wl, s1wr, wc, 128);
    mma_gemm_kernel<<<gemmBlocks, 256>>>(A, wc, D, 64, Ebuf, 64, N_NODES, 128);
    sage_gather_kernel<<<gatherBlocks, 256>>>(roff, esrc, D, s1bl, Ebuf, F,
                                              nullptr, nullptr, nullptr, nullptr, 0);

    // ---- SAGE layer 2 + BN fused ----
    concat_w_kernel<<<(64 * 64 + 255) / 256, 256>>>(s2wl, s2wr, wc, 64);
    mma_gemm_kernel<<<gemmBlocks, 256>>>(F, wc, D, 64, Ebuf, 64, N_NODES, 64);
    sage_gather_kernel<<<gatherBlocks, 256>>>(roff, esrc, D, s2bl, Ebuf, out,
                                              bng, bnb, bnm, bnv, 1);
}